// round 3
// baseline (speedup 1.0000x reference)
#include <cuda_runtime.h>

#define N_NODES 100000
#define N_EDGES 600000
#define CH 128
#define NF (N_NODES * CH)

// ---------------- scratch (no allocations allowed) ----------------
__device__ float g_deg_inv[N_NODES];
__device__ int   g_deg[N_NODES];
__device__ float g_agg[NF];          // aggregation buffer (layers 2,3)
__device__ float g_h1[NF];           // layer-1 output
__device__ float g_h2[NF];           // layer-2 output
__device__ float g_agg3[N_NODES * 3];

// ---------------- degree + layer-1 aggregation ----------------
__global__ void k_zero_deg_agg3() {
    int i = blockIdx.x * blockDim.x + threadIdx.x;
    if (i < N_NODES) {
        g_deg[i] = 0;
        g_agg3[3 * i + 0] = 0.f;
        g_agg3[3 * i + 1] = 0.f;
        g_agg3[3 * i + 2] = 0.f;
    }
}

// one pass over edges: degree count + 3-dim feature scatter
__global__ void k_deg_scatter3(const float* __restrict__ x,
                               const int* __restrict__ src,
                               const int* __restrict__ dst) {
    int e = blockIdx.x * blockDim.x + threadIdx.x;
    if (e < N_EDGES) {
        int s = __ldg(&src[e]);
        int d = __ldg(&dst[e]);
        float x0 = __ldg(&x[3 * s + 0]);
        float x1 = __ldg(&x[3 * s + 1]);
        float x2 = __ldg(&x[3 * s + 2]);
        atomicAdd(&g_deg[d], 1);
        atomicAdd(&g_agg3[3 * d + 0], x0);
        atomicAdd(&g_agg3[3 * d + 1], x1);
        atomicAdd(&g_agg3[3 * d + 2], x2);
    }
}

__global__ void k_deginv() {
    int i = blockIdx.x * blockDim.x + threadIdx.x;
    if (i < N_NODES) {
        int d = g_deg[i];
        g_deg_inv[i] = d > 0 ? 1.0f / (float)d : 0.0f;
    }
}

// layer 1: out = relu((agg3*deginv)@W1l + x@W1r + b1), K=3 so do it directly
__global__ void k_layer1(const float* __restrict__ x,
                         const float* __restrict__ W1l,
                         const float* __restrict__ W1r,
                         const float* __restrict__ b1) {
    __shared__ float wl[3 * CH], wr[3 * CH], bs[CH];
    int c = threadIdx.x;  // 0..127
    wl[c]       = W1l[c];
    wl[c + 128] = W1l[c + 128];
    wl[c + 256] = W1l[c + 256];
    wr[c]       = W1r[c];
    wr[c + 128] = W1r[c + 128];
    wr[c + 256] = W1r[c + 256];
    bs[c]       = b1[c];
    __syncthreads();
    for (int n = blockIdx.x; n < N_NODES; n += gridDim.x) {
        float s  = g_deg_inv[n];
        float a0 = g_agg3[3 * n + 0] * s;
        float a1 = g_agg3[3 * n + 1] * s;
        float a2 = g_agg3[3 * n + 2] * s;
        float x0 = __ldg(&x[3 * n + 0]);
        float x1 = __ldg(&x[3 * n + 1]);
        float x2 = __ldg(&x[3 * n + 2]);
        float v = a0 * wl[c] + a1 * wl[c + 128] + a2 * wl[c + 256]
                + x0 * wr[c] + x1 * wr[c + 128] + x2 * wr[c + 256] + bs[c];
        g_h1[(size_t)n * CH + c] = fmaxf(v, 0.f);
    }
}

// ---------------- 128-wide aggregation ----------------
__global__ void k_zero_agg() {
    int i = blockIdx.x * blockDim.x + threadIdx.x;
    if (i < NF / 4) reinterpret_cast<float4*>(g_agg)[i] = make_float4(0.f, 0.f, 0.f, 0.f);
}

// one warp per edge; each lane moves one float4 (128 ch = 32 lanes * 4)
__global__ void k_scatter(int insel,
                          const int* __restrict__ src,
                          const int* __restrict__ dst) {
    const float* __restrict__ hin = insel ? g_h2 : g_h1;
    int idx = blockIdx.x * blockDim.x + threadIdx.x;
    int e = idx >> 5;
    int c = (idx & 31) << 2;
    if (e < N_EDGES) {
        int s = __ldg(&src[e]);
        int d = __ldg(&dst[e]);
        float4 v = *reinterpret_cast<const float4*>(hin + (size_t)s * CH + c);
        float* p = g_agg + (size_t)d * CH + c;
        asm volatile("red.global.add.v4.f32 [%0], {%1, %2, %3, %4};"
                     :: "l"(p), "f"(v.x), "f"(v.y), "f"(v.z), "f"(v.w)
                     : "memory");
    }
}

// ---------------- fused GEMM: out = relu((agg*deginv)@Wl + hin@Wr + b) ----------------
// BM=128, BN=128, BK=8, TM=8, TN=8, 256 threads
__global__ __launch_bounds__(256, 2) void k_gemm(int insel, int outsel,
                                                 const float* __restrict__ Wl,
                                                 const float* __restrict__ Wr,
                                                 const float* __restrict__ bias,
                                                 float* __restrict__ extout) {
    const float* __restrict__ hin = insel ? g_h2 : g_h1;
    float* __restrict__ out = outsel ? extout : g_h2;

    __shared__ float As[8][128];   // transposed tile: As[k][m]
    __shared__ float Bs[8][128];   // Bs[k][n]

    const int tid = threadIdx.x;
    const int block_m = blockIdx.x * 128;

    const int tr = tid / 16;        // 0..15 -> rows tr*8
    const int tc = tid % 16;        // 0..15 -> cols tc*8
    const int tr8 = tr * 8;
    const int tc8 = tc * 8;

    // loader coords
    const int aRow = tid / 2;            // 0..127
    const int aCol = (tid % 2) * 4;      // 0 or 4
    const int bRow = tid / 32;           // 0..7
    const int bCol = (tid % 32) * 4;     // 0..124

    int gr = block_m + aRow;
    if (gr >= N_NODES) gr = N_NODES - 1;
    const float dscale = g_deg_inv[gr];

    float acc[8][8];
#pragma unroll
    for (int i = 0; i < 8; i++)
#pragma unroll
        for (int j = 0; j < 8; j++) acc[i][j] = 0.f;

#pragma unroll 1
    for (int phase = 0; phase < 2; ++phase) {
        const float* __restrict__ A = (phase == 0) ? g_agg : hin;
        const float* __restrict__ B = (phase == 0) ? Wl : Wr;
        const float ascale = (phase == 0) ? dscale : 1.0f;

#pragma unroll 1
        for (int k0 = 0; k0 < 128; k0 += 8) {
            float4 av = *reinterpret_cast<const float4*>(&A[(size_t)gr * 128 + k0 + aCol]);
            av.x *= ascale; av.y *= ascale; av.z *= ascale; av.w *= ascale;
            As[aCol + 0][aRow] = av.x;
            As[aCol + 1][aRow] = av.y;
            As[aCol + 2][aRow] = av.z;
            As[aCol + 3][aRow] = av.w;

            float4 bv = *reinterpret_cast<const float4*>(&B[(size_t)(k0 + bRow) * 128 + bCol]);
            *reinterpret_cast<float4*>(&Bs[bRow][bCol]) = bv;

            __syncthreads();

#pragma unroll
            for (int k = 0; k < 8; ++k) {
                float4 a0 = *reinterpret_cast<const float4*>(&As[k][tr8]);
                float4 a1 = *reinterpret_cast<const float4*>(&As[k][tr8 + 4]);
                float4 b0 = *reinterpret_cast<const float4*>(&Bs[k][tc8]);
                float4 b1 = *reinterpret_cast<const float4*>(&Bs[k][tc8 + 4]);
                float af[8] = {a0.x, a0.y, a0.z, a0.w, a1.x, a1.y, a1.z, a1.w};
                float bf[8] = {b0.x, b0.y, b0.z, b0.w, b1.x, b1.y, b1.z, b1.w};
#pragma unroll
                for (int i = 0; i < 8; i++)
#pragma unroll
                    for (int j = 0; j < 8; j++) acc[i][j] += af[i] * bf[j];
            }
            __syncthreads();
        }
    }

    // epilogue: + bias, relu, store
    float bj[8];
#pragma unroll
    for (int j = 0; j < 8; j++) bj[j] = __ldg(&bias[tc8 + j]);

#pragma unroll
    for (int i = 0; i < 8; i++) {
        int r = block_m + tr8 + i;
        if (r < N_NODES) {
            float4 o0, o1;
            o0.x = fmaxf(acc[i][0] + bj[0], 0.f);
            o0.y = fmaxf(acc[i][1] + bj[1], 0.f);
            o0.z = fmaxf(acc[i][2] + bj[2], 0.f);
            o0.w = fmaxf(acc[i][3] + bj[3], 0.f);
            o1.x = fmaxf(acc[i][4] + bj[4], 0.f);
            o1.y = fmaxf(acc[i][5] + bj[5], 0.f);
            o1.z = fmaxf(acc[i][6] + bj[6], 0.f);
            o1.w = fmaxf(acc[i][7] + bj[7], 0.f);
            *reinterpret_cast<float4*>(&out[(size_t)r * 128 + tc8]) = o0;
            *reinterpret_cast<float4*>(&out[(size_t)r * 128 + tc8 + 4]) = o1;
        }
    }
}

// ---------------- launch ----------------
extern "C" void kernel_launch(void* const* d_in, const int* in_sizes, int n_in,
                              void* d_out, int out_size) {
    const float* x   = (const float*)d_in[0];
    const int*   ei  = (const int*)d_in[1];
    const float* W1l = (const float*)d_in[2];
    const float* W1r = (const float*)d_in[3];
    const float* b1  = (const float*)d_in[4];
    const float* W2l = (const float*)d_in[5];
    const float* W2r = (const float*)d_in[6];
    const float* b2  = (const float*)d_in[7];
    const float* W3l = (const float*)d_in[8];
    const float* W3r = (const float*)d_in[9];
    const float* b3  = (const float*)d_in[10];
    float* out = (float*)d_out;

    const int* src = ei;
    const int* dst = ei + N_EDGES;

    const int TB = 256;
    const int grid_nodes = (N_NODES + TB - 1) / TB;
    const int grid_edges = (N_EDGES + TB - 1) / TB;
    const int grid_zero  = (NF / 4 + TB - 1) / TB;
    const int grid_scat  = (N_EDGES * 32 + TB - 1) / TB;   // 19.2M threads, fits int
    const int gemm_blocks = (N_NODES + 127) / 128;

    // degree + layer-1 aggregation (3-dim space, before the linear: linearity)
    k_zero_deg_agg3<<<grid_nodes, TB>>>();
    k_deg_scatter3<<<grid_edges, TB>>>(x, src, dst);
    k_deginv<<<grid_nodes, TB>>>();
    k_layer1<<<2048, 128>>>(x, W1l, W1r, b1);                 // -> g_h1

    // layer 2: g_h1 -> g_h2
    k_zero_agg<<<grid_zero, TB>>>();
    k_scatter<<<grid_scat, TB>>>(0, src, dst);
    k_gemm<<<gemm_blocks, 256>>>(0, 0, W2l, W2r, b2, out);

    // layer 3: g_h2 -> out
    k_zero_agg<<<grid_zero, TB>>>();
    k_scatter<<<grid_scat, TB>>>(1, src, dst);
    k_gemm<<<gemm_blocks, 256>>>(1, 1, W3l, W3r, b3, out);
}

// round 11
// speedup vs baseline: 1.5172x; 1.5172x over previous
#include <cuda_runtime.h>
#include <cstdint>

#define N_NODES 100000
#define N_EDGES 600000
#define CH 128
#define NF (N_NODES * CH)

// ---------------- scratch (no allocations allowed) ----------------
__device__ float g_deg_inv[N_NODES];
__device__ int   g_deg[N_NODES];
__device__ float g_agg[NF];          // aggregation buffer (layers 2,3)
__device__ float g_h1[NF];           // layer-1 output
__device__ float g_h2[NF];           // layer-2 output
__device__ float g_agg3[N_NODES * 3];

// ---------------- degree + layer-1 aggregation ----------------
__global__ void k_zero_deg_agg3() {
    int i = blockIdx.x * blockDim.x + threadIdx.x;
    if (i < N_NODES) {
        g_deg[i] = 0;
        g_agg3[3 * i + 0] = 0.f;
        g_agg3[3 * i + 1] = 0.f;
        g_agg3[3 * i + 2] = 0.f;
    }
}

__global__ void k_deg_scatter3(const float* __restrict__ x,
                               const int* __restrict__ src,
                               const int* __restrict__ dst) {
    int e = blockIdx.x * blockDim.x + threadIdx.x;
    if (e < N_EDGES) {
        int s = __ldg(&src[e]);
        int d = __ldg(&dst[e]);
        float x0 = __ldg(&x[3 * s + 0]);
        float x1 = __ldg(&x[3 * s + 1]);
        float x2 = __ldg(&x[3 * s + 2]);
        atomicAdd(&g_deg[d], 1);
        atomicAdd(&g_agg3[3 * d + 0], x0);
        atomicAdd(&g_agg3[3 * d + 1], x1);
        atomicAdd(&g_agg3[3 * d + 2], x2);
    }
}

__global__ void k_deginv() {
    int i = blockIdx.x * blockDim.x + threadIdx.x;
    if (i < N_NODES) {
        int d = g_deg[i];
        g_deg_inv[i] = d > 0 ? 1.0f / (float)d : 0.0f;
    }
}

// layer 1: out = relu((agg3*deginv)@W1l + x@W1r + b1), K=3 so do it directly
__global__ void k_layer1(const float* __restrict__ x,
                         const float* __restrict__ W1l,
                         const float* __restrict__ W1r,
                         const float* __restrict__ b1) {
    __shared__ float wl[3 * CH], wr[3 * CH], bs[CH];
    int c = threadIdx.x;  // 0..127
    wl[c]       = W1l[c];
    wl[c + 128] = W1l[c + 128];
    wl[c + 256] = W1l[c + 256];
    wr[c]       = W1r[c];
    wr[c + 128] = W1r[c + 128];
    wr[c + 256] = W1r[c + 256];
    bs[c]       = b1[c];
    __syncthreads();
    for (int n = blockIdx.x; n < N_NODES; n += gridDim.x) {
        float s  = g_deg_inv[n];
        float a0 = g_agg3[3 * n + 0] * s;
        float a1 = g_agg3[3 * n + 1] * s;
        float a2 = g_agg3[3 * n + 2] * s;
        float x0 = __ldg(&x[3 * n + 0]);
        float x1 = __ldg(&x[3 * n + 1]);
        float x2 = __ldg(&x[3 * n + 2]);
        float v = a0 * wl[c] + a1 * wl[c + 128] + a2 * wl[c + 256]
                + x0 * wr[c] + x1 * wr[c + 128] + x2 * wr[c + 256] + bs[c];
        g_h1[(size_t)n * CH + c] = fmaxf(v, 0.f);
    }
}

// ---------------- 128-wide aggregation ----------------
__global__ void k_zero_agg() {
    int i = blockIdx.x * blockDim.x + threadIdx.x;
    if (i < NF / 4) reinterpret_cast<float4*>(g_agg)[i] = make_float4(0.f, 0.f, 0.f, 0.f);
}

// one warp per edge; each lane moves one float4 (128 ch = 32 lanes * 4)
__global__ void k_scatter(int insel,
                          const int* __restrict__ src,
                          const int* __restrict__ dst) {
    const float* __restrict__ hin = insel ? g_h2 : g_h1;
    int idx = blockIdx.x * blockDim.x + threadIdx.x;
    int e = idx >> 5;
    int c = (idx & 31) << 2;
    if (e < N_EDGES) {
        int s = __ldg(&src[e]);
        int d = __ldg(&dst[e]);
        float4 v = *reinterpret_cast<const float4*>(hin + (size_t)s * CH + c);
        float* p = g_agg + (size_t)d * CH + c;
        asm volatile("red.global.add.v4.f32 [%0], {%1, %2, %3, %4};"
                     :: "l"(p), "f"(v.x), "f"(v.y), "f"(v.z), "f"(v.w)
                     : "memory");
    }
}

// ---------------- tf32 tensor-core GEMM ----------------
// out = relu((agg*deginv)@Wl + hin@Wr + b); then zero this block's g_agg slice.
// BM=128, BN=128, BK=32, 256 threads (8 warps), warp tile 32x64 (2x8 m16n8k8).
__device__ __forceinline__ uint32_t f2tf32(float f) {
    uint32_t u;
    asm("cvt.rna.tf32.f32 %0, %1;" : "=r"(u) : "f"(f));
    return u;
}

#define AP 36    // As pitch (words): 32 k-words per row + 4 pad, conflict-free frags
#define BP 132   // Bs pitch (words): 128 n-words per k-row + 4 pad

__global__ __launch_bounds__(256, 2) void k_gemm_tc(int insel, int outsel,
                                                    const float* __restrict__ Wl,
                                                    const float* __restrict__ Wr,
                                                    const float* __restrict__ bias,
                                                    float* __restrict__ extout) {
    const float* __restrict__ hin = insel ? g_h2 : g_h1;
    float* __restrict__ out = outsel ? extout : g_h2;

    __shared__ uint32_t As[128 * AP];   // [m:128][k:32] pitch 36
    __shared__ uint32_t Bs[32 * BP];    // [k:32][n:128] pitch 132

    const int tid  = threadIdx.x;
    const int wid  = tid >> 5;
    const int lane = tid & 31;
    const int warp_m = wid >> 1;      // 0..3 -> 32-row strip
    const int warp_n = wid & 1;       // 0..1 -> 64-col strip
    const int tg  = lane >> 2;        // 0..7
    const int tig = lane & 3;         // 0..3

    const int block_m = blockIdx.x * 128;

    // A-loader coords: 4 passes of (32 rows x 32 cols) float4 each
    const int lrow = tid >> 3;          // 0..31
    const int lcol = (tid & 7) << 2;    // 0,4,...,28

    // precompute clamped A rows + deg scales (rows constant across k-chunks)
    int arow[4]; float ascale0[4];
#pragma unroll
    for (int p = 0; p < 4; ++p) {
        int r = block_m + lrow + 32 * p;
        if (r >= N_NODES) r = N_NODES - 1;
        arow[p] = r;
        ascale0[p] = g_deg_inv[r];
    }

    float acc[2][8][4];
#pragma unroll
    for (int mt = 0; mt < 2; ++mt)
#pragma unroll
        for (int nt = 0; nt < 8; ++nt)
#pragma unroll
            for (int i = 0; i < 4; ++i) acc[mt][nt][i] = 0.f;

#pragma unroll 1
    for (int phase = 0; phase < 2; ++phase) {
        const float* __restrict__ A = (phase == 0) ? g_agg : hin;
        const float* __restrict__ B = (phase == 0) ? Wl : Wr;

#pragma unroll 1
        for (int k0 = 0; k0 < 128; k0 += 32) {
            // load A tile (128 x 32) -> As, scaled + tf32-converted
#pragma unroll
            for (int p = 0; p < 4; ++p) {
                float sc = (phase == 0) ? ascale0[p] : 1.0f;
                float4 v = *reinterpret_cast<const float4*>(
                    &A[(size_t)arow[p] * 128 + k0 + lcol]);
                int ro = (lrow + 32 * p) * AP + lcol;
                As[ro + 0] = f2tf32(v.x * sc);
                As[ro + 1] = f2tf32(v.y * sc);
                As[ro + 2] = f2tf32(v.z * sc);
                As[ro + 3] = f2tf32(v.w * sc);
            }
            // load B tile (32 x 128) -> Bs (row k, col n); 4 passes of 8 k-rows
            {
                const int bcol4 = (tid & 31) << 2;   // 0..124
                const int bkk   = tid >> 5;          // 0..7
#pragma unroll
                for (int p = 0; p < 4; ++p) {
                    int k = bkk + 8 * p;
                    float4 v = *reinterpret_cast<const float4*>(
                        &B[(size_t)(k0 + k) * 128 + bcol4]);
                    int bo = k * BP + bcol4;
                    Bs[bo + 0] = f2tf32(v.x);
                    Bs[bo + 1] = f2tf32(v.y);
                    Bs[bo + 2] = f2tf32(v.z);
                    Bs[bo + 3] = f2tf32(v.w);
                }
            }
            __syncthreads();

            // 4 k8 steps of m16n8k8 tf32 mma
#pragma unroll
            for (int ks = 0; ks < 4; ++ks) {
                const int kb = ks * 8;
                uint32_t a[2][4];
#pragma unroll
                for (int mt = 0; mt < 2; ++mt) {
                    int r = warp_m * 32 + mt * 16;
                    a[mt][0] = As[(r + tg)     * AP + kb + tig];
                    a[mt][1] = As[(r + tg + 8) * AP + kb + tig];
                    a[mt][2] = As[(r + tg)     * AP + kb + tig + 4];
                    a[mt][3] = As[(r + tg + 8) * AP + kb + tig + 4];
                }
#pragma unroll
                for (int nt = 0; nt < 8; ++nt) {
                    int c = warp_n * 64 + nt * 8 + tg;
                    uint32_t b0 = Bs[(kb + tig)     * BP + c];
                    uint32_t b1 = Bs[(kb + tig + 4) * BP + c];
#pragma unroll
                    for (int mt = 0; mt < 2; ++mt) {
                        asm volatile(
                            "mma.sync.aligned.m16n8k8.row.col.f32.tf32.tf32.f32 "
                            "{%0,%1,%2,%3}, {%4,%5,%6,%7}, {%8,%9}, {%0,%1,%2,%3};"
                            : "+f"(acc[mt][nt][0]), "+f"(acc[mt][nt][1]),
                              "+f"(acc[mt][nt][2]), "+f"(acc[mt][nt][3])
                            : "r"(a[mt][0]), "r"(a[mt][1]), "r"(a[mt][2]), "r"(a[mt][3]),
                              "r"(b0), "r"(b1));
                    }
                }
            }
            __syncthreads();
        }
    }

    // epilogue: + bias, relu, store (float2 per row-fragment)
#pragma unroll
    for (int mt = 0; mt < 2; ++mt) {
        int r0 = block_m + warp_m * 32 + mt * 16 + tg;
        int r1 = r0 + 8;
#pragma unroll
        for (int nt = 0; nt < 8; ++nt) {
            int c = warp_n * 64 + nt * 8 + 2 * tig;
            float bb0 = __ldg(&bias[c]);
            float bb1 = __ldg(&bias[c + 1]);
            if (r0 < N_NODES) {
                float2 o;
                o.x = fmaxf(acc[mt][nt][0] + bb0, 0.f);
                o.y = fmaxf(acc[mt][nt][1] + bb1, 0.f);
                *reinterpret_cast<float2*>(&out[(size_t)r0 * 128 + c]) = o;
            }
            if (r1 < N_NODES) {
                float2 o;
                o.x = fmaxf(acc[mt][nt][2] + bb0, 0.f);
                o.y = fmaxf(acc[mt][nt][3] + bb1, 0.f);
                *reinterpret_cast<float2*>(&out[(size_t)r1 * 128 + c]) = o;
            }
        }
    }

    // zero this block's g_agg slice for the next aggregation pass
    {
        int zr = block_m + (tid >> 1);
        if (zr < N_NODES) {
            float4* p = reinterpret_cast<float4*>(g_agg + (size_t)zr * 128 + (tid & 1) * 64);
#pragma unroll
            for (int i = 0; i < 16; ++i) p[i] = make_float4(0.f, 0.f, 0.f, 0.f);
        }
    }
}

// ---------------- launch ----------------
extern "C" void kernel_launch(void* const* d_in, const int* in_sizes, int n_in,
                              void* d_out, int out_size) {
    const float* x   = (const float*)d_in[0];
    const int*   ei  = (const int*)d_in[1];
    const float* W1l = (const float*)d_in[2];
    const float* W1r = (const float*)d_in[3];
    const float* b1  = (const float*)d_in[4];
    const float* W2l = (const float*)d_in[5];
    const float* W2r = (const float*)d_in[6];
    const float* b2  = (const float*)d_in[7];
    const float* W3l = (const float*)d_in[8];
    const float* W3r = (const float*)d_in[9];
    const float* b3  = (const float*)d_in[10];
    float* out = (float*)d_out;

    const int* src = ei;
    const int* dst = ei + N_EDGES;

    const int TB = 256;
    const int grid_nodes = (N_NODES + TB - 1) / TB;
    const int grid_edges = (N_EDGES + TB - 1) / TB;
    const int grid_zero  = (NF / 4 + TB - 1) / TB;
    const int grid_scat  = (N_EDGES * 32 + TB - 1) / TB;
    const int gemm_blocks = (N_NODES + 127) / 128;

    // degree + layer-1 aggregation (3-dim space, before the linear: linearity)
    k_zero_deg_agg3<<<grid_nodes, TB>>>();
    k_deg_scatter3<<<grid_edges, TB>>>(x, src, dst);
    k_deginv<<<grid_nodes, TB>>>();
    k_layer1<<<2048, 128>>>(x, W1l, W1r, b1);                 // -> g_h1

    // layer 2: g_h1 -> g_h2  (zero_agg only needed on the very first pass;
    // every gemm zeroes g_agg behind itself, keeping replays consistent)
    k_zero_agg<<<grid_zero, TB>>>();
    k_scatter<<<grid_scat, TB>>>(0, src, dst);
    k_gemm_tc<<<gemm_blocks, 256>>>(0, 0, W2l, W2r, b2, out);

    // layer 3: g_h2 -> out (g_agg already zeroed by previous gemm)
    k_scatter<<<grid_scat, TB>>>(1, src, dst);
    k_gemm_tc<<<gemm_blocks, 256>>>(1, 1, W3l, W3r, b3, out);
}